// round 15
// baseline (speedup 1.0000x reference)
#include <cuda_runtime.h>
#include <cuda_fp16.h>
#include <cstdint>

#define BATCH 16
#define IC    512
#define OC    512
#define WD    512
#define HIN   32
#define RES   64
#define YS    65

#define MM   1024
#define KK   512
#define NN   4608
#define MF   (BATCH * MM)

#define TM   256
#define TN   128
#define TKC  128
#define NKC  (KK / TKC)

// ---------------- device scratch (static: no runtime allocation) -----------
__device__ float g_styles[BATCH * IC];
__device__ float g_wsum  [OC * IC];
__device__ float g_dcoef [BATCH * OC];
__device__ __half g_A[(size_t)MF * KK];
__device__ __half g_B[(size_t)NN * KK];
__device__ __half g_ct[(size_t)BATCH * NN * MM];

// ---------------- helpers ----------------------------------------------------
__device__ __forceinline__ uint32_t smem_u32(const void* p) {
    uint32_t a;
    asm("{ .reg .u64 t; cvta.to.shared.u64 t, %1; cvt.u32.u64 %0, t; }"
        : "=r"(a) : "l"(p));
    return a;
}

__device__ __forceinline__ void cp16(uint32_t saddr, const void* g) {
    asm volatile("cp.async.cg.shared.global [%0], [%1], 16;"
                 :: "r"(saddr), "l"(g) : "memory");
}

__device__ __forceinline__ void ldsm4(uint32_t* r, uint32_t addr) {
    asm volatile("ldmatrix.sync.aligned.m8n8.x4.shared.b16 {%0,%1,%2,%3}, [%4];"
                 : "=r"(r[0]), "=r"(r[1]), "=r"(r[2]), "=r"(r[3]) : "r"(addr));
}

__device__ __forceinline__ void mma_fp16(float* d, const uint32_t* a,
                                         uint32_t b0, uint32_t b1) {
    asm volatile(
        "mma.sync.aligned.m16n8k16.row.col.f32.f16.f16.f32 "
        "{%0,%1,%2,%3}, {%4,%5,%6,%7}, {%8,%9}, {%0,%1,%2,%3};"
        : "+f"(d[0]), "+f"(d[1]), "+f"(d[2]), "+f"(d[3])
        : "r"(a[0]), "r"(a[1]), "r"(a[2]), "r"(a[3]), "r"(b0), "r"(b1));
}

#define SA(st)   ((st) * 98304u)
#define SBB(st)  ((st) * 98304u + 65536u)
#define SM_TOTAL_G  196608u
#define EPI_ST   264

// ---------------------------------------------------------------------------
// K1a: styles
// ---------------------------------------------------------------------------
__global__ void k_styles(const float* __restrict__ w,
                         const float* __restrict__ aw,
                         const float* __restrict__ ab) {
    int bx = blockIdx.x, tid = threadIdx.x;
    int b = bx >> 6, icg = bx & 63;
    int warp = tid >> 5, lane = tid & 31;
    int ic = icg * 8 + warp;
    const float* wrow = w  + (size_t)b  * WD;
    const float* arow = aw + (size_t)ic * WD;
    float s = 0.f;
    #pragma unroll 4
    for (int k = lane; k < WD; k += 32) s += wrow[k] * arow[k];
    #pragma unroll
    for (int o = 16; o; o >>= 1) s += __shfl_xor_sync(0xffffffffu, s, o);
    if (lane == 0)
        g_styles[b * IC + ic] = s * 0.04419417382415922f + ab[ic];
}

// ---------------------------------------------------------------------------
// K1b: wsum
// ---------------------------------------------------------------------------
__global__ void k_wsum(const float* __restrict__ cw) {
    int idx = blockIdx.x * 256 + threadIdx.x;
    const float* p = cw + (size_t)idx * 9;
    float s = 0.f;
    #pragma unroll
    for (int k = 0; k < 9; k++) { float v = p[k]; s += v * v; }
    g_wsum[idx] = s;
}

// ---------------------------------------------------------------------------
// K2: fused prep (A style-scaled fp16 transpose; B fp16 reorder; dcoef)
// ---------------------------------------------------------------------------
__global__ void k_prep(const float* __restrict__ x, const float* __restrict__ cw) {
    __shared__ float s[4680];
    int bx = blockIdx.x, tid = threadIdx.x;
    if (bx < 2048) {
        int b  = bx >> 7;
        int m0 = (bx & 15) * 64;
        int k0 = ((bx >> 4) & 7) * 64;
        for (int l = tid; l < 4096; l += 256) {
            int ii = l >> 6, jj = l & 63;
            s[jj * 65 + ii] = x[(((size_t)b * IC + k0 + ii) << 10) + m0 + jj]
                              * g_styles[b * IC + k0 + ii];
        }
        __syncthreads();
        for (int l = tid; l < 4096; l += 256) {
            int mm = l >> 6, kk = l & 63;
            size_t idx = (((size_t)b * MM + m0 + mm) << 9) + k0 + kk;
            g_A[idx] = __float2half_rn(s[mm * 65 + kk]);
        }
    } else if (bx < 2560) {
        int oc = bx - 2048;
        for (int l = tid; l < 4608; l += 256) s[l] = cw[(size_t)oc * 4608 + l];
        __syncthreads();
        for (int l = tid; l < 4608; l += 256) {
            int t = l / 512, k = l & 511;
            size_t idx = (((size_t)oc * 9 + t) << 9) + k;
            g_B[idx] = __float2half_rn(s[k * 9 + t]);
        }
    } else {
        int warp = tid >> 5, lane = tid & 31;
        int pair = (bx - 2560) * 8 + warp;
        int b = pair >> 9, oc = pair & 511;
        float part = 0.f;
        #pragma unroll 4
        for (int ic = lane; ic < IC; ic += 32) {
            float st = g_styles[b * IC + ic];
            part += st * st * g_wsum[oc * IC + ic];
        }
        #pragma unroll
        for (int o = 16; o; o >>= 1) part += __shfl_xor_sync(0xffffffffu, part, o);
        if (lane == 0) g_dcoef[pair] = rsqrtf(part + 1e-8f);
    }
}

// ---------------------------------------------------------------------------
// K3: mma.sync fp16 GEMM v3: CTA 256x128, 8 warps (4m x 2n), warp tile 64x64.
// LDS bytes/MMA: 128 (was 192). TKC=128, 2-stage pipeline (96KB/stage).
// ---------------------------------------------------------------------------
__device__ __forceinline__ void load_chunk_g(uint32_t sb, int m0, int n0,
                                             int c, int st, int tid) {
    size_t kc0 = (size_t)c * TKC;
    #pragma unroll
    for (int i = 0; i < 16; i++) {         // A: 256 rows x 16 (16B) chunks
        int l = tid + i * 256;             // 0..4095
        int r = l >> 4, ch = l & 15;
        const __half* gp = g_A + (((size_t)(m0 + r)) << 9) + kc0 + ch * 8;
        cp16(sb + SA(st) + r * 256u + ((ch ^ (r & 7)) * 16u), gp);
    }
    #pragma unroll
    for (int i = 0; i < 8; i++) {          // B: 128 rows x 16 (16B) chunks
        int l = tid + i * 256;             // 0..2047
        int r = l >> 4, ch = l & 15;
        const __half* gp = g_B + (((size_t)(n0 + r)) << 9) + kc0 + ch * 8;
        cp16(sb + SBB(st) + r * 256u + ((ch ^ (r & 7)) * 16u), gp);
    }
    asm volatile("cp.async.commit_group;" ::: "memory");
}

__global__ void __launch_bounds__(256, 1) k_gemm() {
    extern __shared__ char smem[];
    uint32_t sb = smem_u32(smem);
    int tid = threadIdx.x, wid = tid >> 5, lane = tid & 31;
    int n0 = blockIdx.x * TN;
    int m0 = blockIdx.y * TM;      // flat (b,m): 256 | 1024, so b fixed per CTA

    int wm0 = (wid >> 1) * 64;     // 4 m-warps
    int wn0 = (wid & 1) * 64;      // 2 n-warps

    int mat = lane >> 3, rr = lane & 7;
    int lr  = (mat & 1) * 8 + rr;
    int chi = mat >> 1;

    uint32_t arow = (uint32_t)(wm0 + lr);
    uint32_t brow = (uint32_t)(wn0 + lr);
    uint32_t aswz = arow & 7;
    uint32_t bswz = brow & 7;

    float acc[4][8][4];
    #pragma unroll
    for (int i = 0; i < 4; i++)
        #pragma unroll
        for (int j = 0; j < 8; j++)
            #pragma unroll
            for (int q = 0; q < 4; q++) acc[i][j][q] = 0.f;

    load_chunk_g(sb, m0, n0, 0, 0, tid);

    #pragma unroll 1
    for (int c = 0; c < NKC; c++) {
        int st = c & 1;
        asm volatile("cp.async.wait_group 0;" ::: "memory");
        __syncthreads();
        if (c + 1 < NKC) load_chunk_g(sb, m0, n0, c + 1, st ^ 1, tid);

        #pragma unroll
        for (int s = 0; s < 8; s++) {
            uint32_t kchunk = (uint32_t)(2 * s + chi);
            uint32_t acol = ((kchunk ^ aswz) * 16u);
            uint32_t bcol = ((kchunk ^ bswz) * 16u);

            uint32_t bf[4][4];
            #pragma unroll
            for (int nj2 = 0; nj2 < 4; nj2++)
                ldsm4(bf[nj2], sb + SBB(st) + (brow + nj2 * 16u) * 256u + bcol);

            uint32_t af[4][4];
            #pragma unroll
            for (int mi = 0; mi < 4; mi++)
                ldsm4(af[mi], sb + SA(st) + (arow + mi * 16u) * 256u + acol);

            #pragma unroll
            for (int mi = 0; mi < 4; mi++)
                #pragma unroll
                for (int nj = 0; nj < 8; nj++)
                    mma_fp16(acc[mi][nj], af[mi],
                             bf[nj >> 1][nj & 1], bf[nj >> 1][(nj & 1) + 2]);
        }
    }

    // ---- epilogue: stage fp16 tile in smem, store coalesced ----
    __syncthreads();
    __half* cs = (__half*)smem;          // [128][EPI_ST]
    int g  = lane >> 2;
    int cq = (lane & 3) * 2;
    #pragma unroll
    for (int mi = 0; mi < 4; mi++) {
        #pragma unroll
        for (int nj = 0; nj < 8; nj++) {
            int nl = wn0 + nj * 8 + cq;
            int ml = wm0 + mi * 16 + g;
            cs[nl * EPI_ST + ml]           = __float2half_rn(acc[mi][nj][0]);
            cs[(nl + 1) * EPI_ST + ml]     = __float2half_rn(acc[mi][nj][1]);
            cs[nl * EPI_ST + ml + 8]       = __float2half_rn(acc[mi][nj][2]);
            cs[(nl + 1) * EPI_ST + ml + 8] = __float2half_rn(acc[mi][nj][3]);
        }
    }
    __syncthreads();

    int b    = m0 >> 10;
    int mloc = m0 & 1023;
    __half* gout = g_ct + ((size_t)b * NN + n0) * MM + mloc;
    #pragma unroll
    for (int i = 0; i < 16; i++) {
        int l = tid + i * 256;            // 0..4095
        int row = l >> 5, c16 = l & 31;   // 128 rows x 32 uint4
        uint4 v = *(const uint4*)&cs[row * EPI_ST + c16 * 8];
        *(uint4*)(gout + (size_t)row * MM + c16 * 8) = v;
    }
}

// ---------------------------------------------------------------------------
// K4: separable fused FIR (R12-identical, validated).
// ---------------------------------------------------------------------------
#define HROWS 18
#define HST   68
__global__ void __launch_bounds__(256, 5) k_fir(const float* __restrict__ f,
                                                const float* __restrict__ noise,
                                                const float* __restrict__ bias,
                                                float* __restrict__ out) {
    __shared__ __align__(16) float H[3 * HROWS * HST];

    int z  = blockIdx.x;
    int b  = z >> 10;
    int oc = (z >> 1) & 511;
    int uh = z & 1;
    int u0 = uh << 5;
    int hb = uh ? 15 : -1;
    int tid = threadIdx.x;

    float f00 = f[0];
    float rs  = rsqrtf(f00);
    float gv0 = 2.f * f[0] * rs;
    float gv1 = 2.f * f[1] * rs;
    float gv2 = 2.f * f[2] * rs;
    float gv3 = 2.f * f[3] * rs;

    if (tid < 216) {
        int i   = tid / 72;
        int rem = tid - i * 72;
        int r = rem >> 2, s4 = rem & 3;
        int h = hb + r;

        float Hv[16];
        #pragma unroll
        for (int k = 0; k < 16; k++) Hv[k] = 0.f;

        if (h >= 0 && h < 32) {
            const __half* cb = g_ct + ((size_t)b * NN + (size_t)oc * 9) * MM;
            #pragma unroll
            for (int j = 0; j < 3; j++) {
                const uint2* src = (const uint2*)(cb + (size_t)(i * 3 + j) * MM + h * 32);
                float c[16];
                #pragma unroll
                for (int q = 0; q < 4; q++) {
                    int wb = 8 * s4 - 4 + 4 * q;
                    if (wb >= 0 && wb < 32) {
                        uint2 v = src[wb >> 2];
                        float2 x0 = __half22float2(*(const __half2*)&v.x);
                        float2 x1 = __half22float2(*(const __half2*)&v.y);
                        c[4*q]   = x0.x; c[4*q+1] = x0.y;
                        c[4*q+2] = x1.x; c[4*q+3] = x1.y;
                    } else {
                        c[4*q] = c[4*q+1] = c[4*q+2] = c[4*q+3] = 0.f;
                    }
                }
                #pragma unroll
                for (int k = 0; k < 16; k++) {
                    const int e0 = (j + k + 1) & 1;
                    const int lw = (k - 1 - j + e0) / 2 + 4;
                    float ge0 = e0 ? gv1 : gv0;
                    float ge2 = e0 ? gv3 : gv2;
                    Hv[k] += ge0 * c[lw] + ge2 * c[lw + 1];
                }
            }
        }
        float4* dst = (float4*)&H[(i * HROWS + r) * HST + 16 * s4];
        dst[0] = make_float4(Hv[0],  Hv[1],  Hv[2],  Hv[3]);
        dst[1] = make_float4(Hv[4],  Hv[5],  Hv[6],  Hv[7]);
        dst[2] = make_float4(Hv[8],  Hv[9],  Hv[10], Hv[11]);
        dst[3] = make_float4(Hv[12], Hv[13], Hv[14], Hv[15]);
    }
    __syncthreads();

    float dco = g_dcoef[b * OC + oc];
    int u  = u0 + (tid & 31);
    int vg = tid >> 5;

    float4 r0 = make_float4(0.f, 0.f, 0.f, 0.f);
    float4 r1 = make_float4(0.f, 0.f, 0.f, 0.f);

    #pragma unroll
    for (int i = 0; i < 3; i++) {
        int t  = u - 1 - i;
        int a0 = t & 1;
        int r  = ((t + a0) >> 1) - hb;
        const float* rowA = &H[(i * HROWS + r) * HST + 8 * vg];
        const float* rowB = rowA + HST;
        float ga = a0 ? gv1 : gv0;
        float gb = a0 ? gv3 : gv2;
        float4 A0 = *(const float4*)rowA;
        float4 A1 = *(const float4*)(rowA + 4);
        float4 B0 = *(const float4*)rowB;
        float4 B1 = *(const float4*)(rowB + 4);
        r0.x += ga * A0.x + gb * B0.x;
        r0.y += ga * A0.y + gb * B0.y;
        r0.z += ga * A0.z + gb * B0.z;
        r0.w += ga * A0.w + gb * B0.w;
        r1.x += ga * A1.x + gb * B1.x;
        r1.y += ga * A1.y + gb * B1.y;
        r1.z += ga * A1.z + gb * B1.z;
        r1.w += ga * A1.w + gb * B1.w;
    }

    float bs = bias[oc];
    const float4* nr = (const float4*)(noise + u * RES + vg * 8);
    float4 n0 = nr[0], n1 = nr[1];
    float4 o0, o1;
    {
        float v;
        v = r0.x * dco + n0.x + bs; v = (v > 0.f) ? v : 0.2f * v; o0.x = v * 1.4142135623730951f;
        v = r0.y * dco + n0.y + bs; v = (v > 0.f) ? v : 0.2f * v; o0.y = v * 1.4142135623730951f;
        v = r0.z * dco + n0.z + bs; v = (v > 0.f) ? v : 0.2f * v; o0.z = v * 1.4142135623730951f;
        v = r0.w * dco + n0.w + bs; v = (v > 0.f) ? v : 0.2f * v; o0.w = v * 1.4142135623730951f;
        v = r1.x * dco + n1.x + bs; v = (v > 0.f) ? v : 0.2f * v; o1.x = v * 1.4142135623730951f;
        v = r1.y * dco + n1.y + bs; v = (v > 0.f) ? v : 0.2f * v; o1.y = v * 1.4142135623730951f;
        v = r1.z * dco + n1.z + bs; v = (v > 0.f) ? v : 0.2f * v; o1.z = v * 1.4142135623730951f;
        v = r1.w * dco + n1.w + bs; v = (v > 0.f) ? v : 0.2f * v; o1.w = v * 1.4142135623730951f;
    }
    float4* orow = (float4*)(out + (((size_t)(b * OC + oc) * RES) + u) * RES + vg * 8);
    orow[0] = o0;
    orow[1] = o1;
}

// ---------------------------------------------------------------------------
extern "C" void kernel_launch(void* const* d_in, const int* in_sizes, int n_in,
                              void* d_out, int out_size) {
    const float* x     = (const float*)d_in[0];
    const float* w     = (const float*)d_in[1];
    const float* aw    = (const float*)d_in[2];
    const float* ab    = (const float*)d_in[3];
    const float* cw    = (const float*)d_in[4];
    const float* bias  = (const float*)d_in[5];
    const float* noise = (const float*)d_in[6];
    const float* f     = (const float*)d_in[7];
    float* out = (float*)d_out;

    cudaFuncSetAttribute(k_gemm, cudaFuncAttributeMaxDynamicSharedMemorySize, SM_TOTAL_G);
    cudaFuncSetAttribute(k_fir, cudaFuncAttributePreferredSharedMemoryCarveout, 100);

    // k_gemm is the 4th launch -> lands in the ncu capture slot
    k_styles<<<1024, 256>>>(w, aw, ab);
    k_wsum  <<<1024, 256>>>(cw);
    k_prep  <<<3584, 256>>>(x, cw);
    k_gemm  <<<dim3(NN / TN, MF / TM), 256, SM_TOTAL_G>>>();
    k_fir   <<<BATCH * OC * 2, 256>>>(f, noise, bias, out);
}

// round 16
// speedup vs baseline: 1.5545x; 1.5545x over previous
#include <cuda_runtime.h>
#include <cuda_fp16.h>
#include <cstdint>

#define BATCH 16
#define IC    512
#define OC    512
#define WD    512
#define HIN   32
#define RES   64
#define YS    65

#define MM   1024
#define KK   512
#define NN   4608
#define MF   (BATCH * MM)

#define TM   256
#define TN   128
#define TKC  128
#define NKC  (KK / TKC)

// ---------------- device scratch (static: no runtime allocation) -----------
__device__ float g_styles[BATCH * IC];
__device__ float g_wsum  [OC * IC];
__device__ float g_dcoef [BATCH * OC];
__device__ __half g_A[(size_t)MF * KK];
__device__ __half g_B[(size_t)NN * KK];
__device__ __half g_ct[(size_t)BATCH * NN * MM];

// ---------------- helpers ----------------------------------------------------
__device__ __forceinline__ uint32_t smem_u32(const void* p) {
    uint32_t a;
    asm("{ .reg .u64 t; cvta.to.shared.u64 t, %1; cvt.u32.u64 %0, t; }"
        : "=r"(a) : "l"(p));
    return a;
}

__device__ __forceinline__ void cp16(uint32_t saddr, const void* g) {
    asm volatile("cp.async.cg.shared.global [%0], [%1], 16;"
                 :: "r"(saddr), "l"(g) : "memory");
}

__device__ __forceinline__ void ldsm4(uint32_t* r, uint32_t addr) {
    asm volatile("ldmatrix.sync.aligned.m8n8.x4.shared.b16 {%0,%1,%2,%3}, [%4];"
                 : "=r"(r[0]), "=r"(r[1]), "=r"(r[2]), "=r"(r[3]) : "r"(addr));
}

__device__ __forceinline__ void mma_fp16(float* d, const uint32_t* a,
                                         uint32_t b0, uint32_t b1) {
    asm volatile(
        "mma.sync.aligned.m16n8k16.row.col.f32.f16.f16.f32 "
        "{%0,%1,%2,%3}, {%4,%5,%6,%7}, {%8,%9}, {%0,%1,%2,%3};"
        : "+f"(d[0]), "+f"(d[1]), "+f"(d[2]), "+f"(d[3])
        : "r"(a[0]), "r"(a[1]), "r"(a[2]), "r"(a[3]), "r"(b0), "r"(b1));
}

#define SA(st)   ((st) * 98304u)
#define SBB(st)  ((st) * 98304u + 65536u)
#define SM_TOTAL_G  196608u
#define EPI_ST   264

// ---------------------------------------------------------------------------
// K1: fused styles + wsum (one launch).
//   blocks [0,1024): styles (one warp per (b,ic));  [1024,2048): wsum
// ---------------------------------------------------------------------------
__global__ void k_sw(const float* __restrict__ w,
                     const float* __restrict__ aw,
                     const float* __restrict__ ab,
                     const float* __restrict__ cw) {
    int bx = blockIdx.x, tid = threadIdx.x;
    if (bx < 1024) {
        int b = bx >> 6, icg = bx & 63;
        int warp = tid >> 5, lane = tid & 31;
        int ic = icg * 8 + warp;
        const float* wrow = w  + (size_t)b  * WD;
        const float* arow = aw + (size_t)ic * WD;
        float s = 0.f;
        #pragma unroll 4
        for (int k = lane; k < WD; k += 32) s += wrow[k] * arow[k];
        #pragma unroll
        for (int o = 16; o; o >>= 1) s += __shfl_xor_sync(0xffffffffu, s, o);
        if (lane == 0)
            g_styles[b * IC + ic] = s * 0.04419417382415922f + ab[ic];
    } else {
        int idx = (bx - 1024) * 256 + tid;
        const float* p = cw + (size_t)idx * 9;
        float s = 0.f;
        #pragma unroll
        for (int k = 0; k < 9; k++) { float v = p[k]; s += v * v; }
        g_wsum[idx] = s;
    }
}

// ---------------------------------------------------------------------------
// K2: fused prep (A style-scaled fp16 transpose vectorized; B reorder; dcoef)
// ---------------------------------------------------------------------------
__global__ void k_prep(const float* __restrict__ x, const float* __restrict__ cw) {
    __shared__ float s[4680];           // max(64*65, 4608)
    int bx = blockIdx.x, tid = threadIdx.x;
    if (bx < 2048) {
        int b  = bx >> 7;
        int m0 = (bx & 15) * 64;
        int k0 = ((bx >> 4) & 7) * 64;
        // load: float4 over the contiguous m (jj) dimension
        #pragma unroll
        for (int it = 0; it < 4; it++) {
            int l = tid + it * 256;            // 0..1023
            int ii = l >> 4, jj4 = (l & 15) * 4;
            const float4 xv = *(const float4*)&x[(((size_t)b * IC + k0 + ii) << 10) + m0 + jj4];
            float st = g_styles[b * IC + k0 + ii];
            s[(jj4 + 0) * 65 + ii] = xv.x * st;
            s[(jj4 + 1) * 65 + ii] = xv.y * st;
            s[(jj4 + 2) * 65 + ii] = xv.z * st;
            s[(jj4 + 3) * 65 + ii] = xv.w * st;
        }
        __syncthreads();
        // store: __half2 over k (kk) pairs
        #pragma unroll
        for (int it = 0; it < 8; it++) {
            int l = tid + it * 256;            // 0..2047
            int mm = l >> 5, kk = (l & 31) * 2;
            __half2 hv = __floats2half2_rn(s[mm * 65 + kk], s[mm * 65 + kk + 1]);
            *(__half2*)&g_A[(((size_t)b * MM + m0 + mm) << 9) + k0 + kk] = hv;
        }
    } else if (bx < 2560) {
        int oc = bx - 2048;
        for (int l = tid; l < 4608; l += 256) s[l] = cw[(size_t)oc * 4608 + l];
        __syncthreads();
        for (int l = tid; l < 4608; l += 256) {
            int t = l / 512, k = l & 511;
            size_t idx = (((size_t)oc * 9 + t) << 9) + k;
            g_B[idx] = __float2half_rn(s[k * 9 + t]);
        }
    } else {
        int warp = tid >> 5, lane = tid & 31;
        int pair = (bx - 2560) * 8 + warp;
        int b = pair >> 9, oc = pair & 511;
        float part = 0.f;
        #pragma unroll 4
        for (int ic = lane; ic < IC; ic += 32) {
            float st = g_styles[b * IC + ic];
            part += st * st * g_wsum[oc * IC + ic];
        }
        #pragma unroll
        for (int o = 16; o; o >>= 1) part += __shfl_xor_sync(0xffffffffu, part, o);
        if (lane == 0) g_dcoef[pair] = rsqrtf(part + 1e-8f);
    }
}

// ---------------------------------------------------------------------------
// K3: mma.sync fp16 GEMM (R13 configuration — best measured).
// CTA 256x128, 16 warps (4m x 4n), warp 64x32, TKC=128, 2-stage pipeline,
// smem-staged coalesced fp16 epilogue.
// ---------------------------------------------------------------------------
__device__ __forceinline__ void load_chunk_g(uint32_t sb, int m0, int n0,
                                             int c, int st, int tid) {
    size_t kc0 = (size_t)c * TKC;
    #pragma unroll
    for (int i = 0; i < 8; i++) {
        int l = tid + i * 512;
        int r = l >> 4, ch = l & 15;
        const __half* gp = g_A + (((size_t)(m0 + r)) << 9) + kc0 + ch * 8;
        cp16(sb + SA(st) + r * 256u + ((ch ^ (r & 7)) * 16u), gp);
    }
    #pragma unroll
    for (int i = 0; i < 4; i++) {
        int l = tid + i * 512;
        int r = l >> 4, ch = l & 15;
        const __half* gp = g_B + (((size_t)(n0 + r)) << 9) + kc0 + ch * 8;
        cp16(sb + SBB(st) + r * 256u + ((ch ^ (r & 7)) * 16u), gp);
    }
    asm volatile("cp.async.commit_group;" ::: "memory");
}

__global__ void __launch_bounds__(512, 1) k_gemm() {
    extern __shared__ char smem[];
    uint32_t sb = smem_u32(smem);
    int tid = threadIdx.x, wid = tid >> 5, lane = tid & 31;
    int n0 = blockIdx.x * TN;
    int m0 = blockIdx.y * TM;

    int wm0 = (wid >> 2) * 64;
    int wn0 = (wid & 3) * 32;

    int mat = lane >> 3, rr = lane & 7;
    int lr  = (mat & 1) * 8 + rr;
    int chi = mat >> 1;

    uint32_t arow = (uint32_t)(wm0 + lr);
    uint32_t brow = (uint32_t)(wn0 + lr);
    uint32_t aswz = arow & 7;
    uint32_t bswz = brow & 7;

    float acc[4][4][4];
    #pragma unroll
    for (int i = 0; i < 4; i++)
        #pragma unroll
        for (int j = 0; j < 4; j++)
            #pragma unroll
            for (int q = 0; q < 4; q++) acc[i][j][q] = 0.f;

    load_chunk_g(sb, m0, n0, 0, 0, tid);

    #pragma unroll 1
    for (int c = 0; c < NKC; c++) {
        int st = c & 1;
        asm volatile("cp.async.wait_group 0;" ::: "memory");
        __syncthreads();
        if (c + 1 < NKC) load_chunk_g(sb, m0, n0, c + 1, st ^ 1, tid);

        #pragma unroll
        for (int s = 0; s < 8; s++) {
            uint32_t kchunk = (uint32_t)(2 * s + chi);
            uint32_t acol = ((kchunk ^ aswz) * 16u);
            uint32_t bcol = ((kchunk ^ bswz) * 16u);

            uint32_t bf[2][4];
            #pragma unroll
            for (int nj2 = 0; nj2 < 2; nj2++)
                ldsm4(bf[nj2], sb + SBB(st) + (brow + nj2 * 16u) * 256u + bcol);

            uint32_t af[4][4];
            #pragma unroll
            for (int mi = 0; mi < 4; mi++)
                ldsm4(af[mi], sb + SA(st) + (arow + mi * 16u) * 256u + acol);

            #pragma unroll
            for (int mi = 0; mi < 4; mi++)
                #pragma unroll
                for (int nj = 0; nj < 4; nj++)
                    mma_fp16(acc[mi][nj], af[mi],
                             bf[nj >> 1][nj & 1], bf[nj >> 1][(nj & 1) + 2]);
        }
    }

    __syncthreads();
    __half* cs = (__half*)smem;
    int g  = lane >> 2;
    int cq = (lane & 3) * 2;
    #pragma unroll
    for (int mi = 0; mi < 4; mi++) {
        #pragma unroll
        for (int nj = 0; nj < 4; nj++) {
            int nl = wn0 + nj * 8 + cq;
            int ml = wm0 + mi * 16 + g;
            cs[nl * EPI_ST + ml]           = __float2half_rn(acc[mi][nj][0]);
            cs[(nl + 1) * EPI_ST + ml]     = __float2half_rn(acc[mi][nj][1]);
            cs[nl * EPI_ST + ml + 8]       = __float2half_rn(acc[mi][nj][2]);
            cs[(nl + 1) * EPI_ST + ml + 8] = __float2half_rn(acc[mi][nj][3]);
        }
    }
    __syncthreads();

    int b    = m0 >> 10;
    int mloc = m0 & 1023;
    __half* gout = g_ct + ((size_t)b * NN + n0) * MM + mloc;
    #pragma unroll
    for (int i = 0; i < 8; i++) {
        int l = tid + i * 512;
        int row = l >> 5, c16 = l & 31;
        uint4 v = *(const uint4*)&cs[row * EPI_ST + c16 * 8];
        *(uint4*)(gout + (size_t)row * MM + c16 * 8) = v;
    }
}

// ---------------------------------------------------------------------------
// K4: separable fused FIR (R12-identical, validated).
// ---------------------------------------------------------------------------
#define HROWS 18
#define HST   68
__global__ void __launch_bounds__(256, 5) k_fir(const float* __restrict__ f,
                                                const float* __restrict__ noise,
                                                const float* __restrict__ bias,
                                                float* __restrict__ out) {
    __shared__ __align__(16) float H[3 * HROWS * HST];

    int z  = blockIdx.x;
    int b  = z >> 10;
    int oc = (z >> 1) & 511;
    int uh = z & 1;
    int u0 = uh << 5;
    int hb = uh ? 15 : -1;
    int tid = threadIdx.x;

    float f00 = f[0];
    float rs  = rsqrtf(f00);
    float gv0 = 2.f * f[0] * rs;
    float gv1 = 2.f * f[1] * rs;
    float gv2 = 2.f * f[2] * rs;
    float gv3 = 2.f * f[3] * rs;

    if (tid < 216) {
        int i   = tid / 72;
        int rem = tid - i * 72;
        int r = rem >> 2, s4 = rem & 3;
        int h = hb + r;

        float Hv[16];
        #pragma unroll
        for (int k = 0; k < 16; k++) Hv[k] = 0.f;

        if (h >= 0 && h < 32) {
            const __half* cb = g_ct + ((size_t)b * NN + (size_t)oc * 9) * MM;
            #pragma unroll
            for (int j = 0; j < 3; j++) {
                const uint2* src = (const uint2*)(cb + (size_t)(i * 3 + j) * MM + h * 32);
                float c[16];
                #pragma unroll
                for (int q = 0; q < 4; q++) {
                    int wb = 8 * s4 - 4 + 4 * q;
                    if (wb >= 0 && wb < 32) {
                        uint2 v = src[wb >> 2];
                        float2 x0 = __half22float2(*(const __half2*)&v.x);
                        float2 x1 = __half22float2(*(const __half2*)&v.y);
                        c[4*q]   = x0.x; c[4*q+1] = x0.y;
                        c[4*q+2] = x1.x; c[4*q+3] = x1.y;
                    } else {
                        c[4*q] = c[4*q+1] = c[4*q+2] = c[4*q+3] = 0.f;
                    }
                }
                #pragma unroll
                for (int k = 0; k < 16; k++) {
                    const int e0 = (j + k + 1) & 1;
                    const int lw = (k - 1 - j + e0) / 2 + 4;
                    float ge0 = e0 ? gv1 : gv0;
                    float ge2 = e0 ? gv3 : gv2;
                    Hv[k] += ge0 * c[lw] + ge2 * c[lw + 1];
                }
            }
        }
        float4* dst = (float4*)&H[(i * HROWS + r) * HST + 16 * s4];
        dst[0] = make_float4(Hv[0],  Hv[1],  Hv[2],  Hv[3]);
        dst[1] = make_float4(Hv[4],  Hv[5],  Hv[6],  Hv[7]);
        dst[2] = make_float4(Hv[8],  Hv[9],  Hv[10], Hv[11]);
        dst[3] = make_float4(Hv[12], Hv[13], Hv[14], Hv[15]);
    }
    __syncthreads();

    float dco = g_dcoef[b * OC + oc];
    int u  = u0 + (tid & 31);
    int vg = tid >> 5;

    float4 r0 = make_float4(0.f, 0.f, 0.f, 0.f);
    float4 r1 = make_float4(0.f, 0.f, 0.f, 0.f);

    #pragma unroll
    for (int i = 0; i < 3; i++) {
        int t  = u - 1 - i;
        int a0 = t & 1;
        int r  = ((t + a0) >> 1) - hb;
        const float* rowA = &H[(i * HROWS + r) * HST + 8 * vg];
        const float* rowB = rowA + HST;
        float ga = a0 ? gv1 : gv0;
        float gb = a0 ? gv3 : gv2;
        float4 A0 = *(const float4*)rowA;
        float4 A1 = *(const float4*)(rowA + 4);
        float4 B0 = *(const float4*)rowB;
        float4 B1 = *(const float4*)(rowB + 4);
        r0.x += ga * A0.x + gb * B0.x;
        r0.y += ga * A0.y + gb * B0.y;
        r0.z += ga * A0.z + gb * B0.z;
        r0.w += ga * A0.w + gb * B0.w;
        r1.x += ga * A1.x + gb * B1.x;
        r1.y += ga * A1.y + gb * B1.y;
        r1.z += ga * A1.z + gb * B1.z;
        r1.w += ga * A1.w + gb * B1.w;
    }

    float bs = bias[oc];
    const float4* nr = (const float4*)(noise + u * RES + vg * 8);
    float4 n0 = nr[0], n1 = nr[1];
    float4 o0, o1;
    {
        float v;
        v = r0.x * dco + n0.x + bs; v = (v > 0.f) ? v : 0.2f * v; o0.x = v * 1.4142135623730951f;
        v = r0.y * dco + n0.y + bs; v = (v > 0.f) ? v : 0.2f * v; o0.y = v * 1.4142135623730951f;
        v = r0.z * dco + n0.z + bs; v = (v > 0.f) ? v : 0.2f * v; o0.z = v * 1.4142135623730951f;
        v = r0.w * dco + n0.w + bs; v = (v > 0.f) ? v : 0.2f * v; o0.w = v * 1.4142135623730951f;
        v = r1.x * dco + n1.x + bs; v = (v > 0.f) ? v : 0.2f * v; o1.x = v * 1.4142135623730951f;
        v = r1.y * dco + n1.y + bs; v = (v > 0.f) ? v : 0.2f * v; o1.y = v * 1.4142135623730951f;
        v = r1.z * dco + n1.z + bs; v = (v > 0.f) ? v : 0.2f * v; o1.z = v * 1.4142135623730951f;
        v = r1.w * dco + n1.w + bs; v = (v > 0.f) ? v : 0.2f * v; o1.w = v * 1.4142135623730951f;
    }
    float4* orow = (float4*)(out + (((size_t)(b * OC + oc) * RES) + u) * RES + vg * 8);
    orow[0] = o0;
    orow[1] = o1;
}

// ---------------------------------------------------------------------------
extern "C" void kernel_launch(void* const* d_in, const int* in_sizes, int n_in,
                              void* d_out, int out_size) {
    const float* x     = (const float*)d_in[0];
    const float* w     = (const float*)d_in[1];
    const float* aw    = (const float*)d_in[2];
    const float* ab    = (const float*)d_in[3];
    const float* cw    = (const float*)d_in[4];
    const float* bias  = (const float*)d_in[5];
    const float* noise = (const float*)d_in[6];
    const float* f     = (const float*)d_in[7];
    float* out = (float*)d_out;

    cudaFuncSetAttribute(k_gemm, cudaFuncAttributeMaxDynamicSharedMemorySize, SM_TOTAL_G);
    cudaFuncSetAttribute(k_fir, cudaFuncAttributePreferredSharedMemoryCarveout, 100);

    k_sw   <<<2048, 256>>>(w, aw, ab, cw);
    k_prep <<<3584, 256>>>(x, cw);
    k_gemm <<<dim3(NN / TN, MF / TM), 512, SM_TOTAL_G>>>();
    k_fir  <<<BATCH * OC * 2, 256>>>(f, noise, bias, out);
}

// round 17
// speedup vs baseline: 1.7933x; 1.1536x over previous
#include <cuda_runtime.h>
#include <cuda_fp16.h>
#include <cstdint>

#define BATCH 16
#define IC    512
#define OC    512
#define WD    512
#define HIN   32
#define RES   64
#define YS    65

#define MM   1024
#define KK   512
#define NN   4608
#define MF   (BATCH * MM)

#define TM   256
#define TN   128
#define TKC  128
#define NKC  (KK / TKC)

// ---------------- device scratch (static: no runtime allocation) -----------
__device__ float g_styles[BATCH * IC];
__device__ float g_wsum  [OC * IC];
__device__ float g_dcoef [BATCH * OC];
__device__ __half g_A[(size_t)MF * KK];
__device__ __half g_B[(size_t)NN * KK];
__device__ __half g_ct[(size_t)BATCH * NN * MM];

// ---------------- helpers ----------------------------------------------------
__device__ __forceinline__ uint32_t smem_u32(const void* p) {
    uint32_t a;
    asm("{ .reg .u64 t; cvta.to.shared.u64 t, %1; cvt.u32.u64 %0, t; }"
        : "=r"(a) : "l"(p));
    return a;
}

__device__ __forceinline__ void cp16(uint32_t saddr, const void* g) {
    asm volatile("cp.async.cg.shared.global [%0], [%1], 16;"
                 :: "r"(saddr), "l"(g) : "memory");
}

__device__ __forceinline__ void ldsm4(uint32_t* r, uint32_t addr) {
    asm volatile("ldmatrix.sync.aligned.m8n8.x4.shared.b16 {%0,%1,%2,%3}, [%4];"
                 : "=r"(r[0]), "=r"(r[1]), "=r"(r[2]), "=r"(r[3]) : "r"(addr));
}

__device__ __forceinline__ void mma_fp16(float* d, const uint32_t* a,
                                         uint32_t b0, uint32_t b1) {
    asm volatile(
        "mma.sync.aligned.m16n8k16.row.col.f32.f16.f16.f32 "
        "{%0,%1,%2,%3}, {%4,%5,%6,%7}, {%8,%9}, {%0,%1,%2,%3};"
        : "+f"(d[0]), "+f"(d[1]), "+f"(d[2]), "+f"(d[3])
        : "r"(a[0]), "r"(a[1]), "r"(a[2]), "r"(a[3]), "r"(b0), "r"(b1));
}

#define SA(st)   ((st) * 98304u)
#define SBB(st)  ((st) * 98304u + 65536u)
#define SM_TOTAL_G  196608u
#define EPI_ST   264

// ---------------------------------------------------------------------------
// K1: fused styles + wsum (one launch).
// ---------------------------------------------------------------------------
__global__ void k_sw(const float* __restrict__ w,
                     const float* __restrict__ aw,
                     const float* __restrict__ ab,
                     const float* __restrict__ cw) {
    int bx = blockIdx.x, tid = threadIdx.x;
    if (bx < 1024) {
        int b = bx >> 6, icg = bx & 63;
        int warp = tid >> 5, lane = tid & 31;
        int ic = icg * 8 + warp;
        const float* wrow = w  + (size_t)b  * WD;
        const float* arow = aw + (size_t)ic * WD;
        float s = 0.f;
        #pragma unroll 4
        for (int k = lane; k < WD; k += 32) s += wrow[k] * arow[k];
        #pragma unroll
        for (int o = 16; o; o >>= 1) s += __shfl_xor_sync(0xffffffffu, s, o);
        if (lane == 0)
            g_styles[b * IC + ic] = s * 0.04419417382415922f + ab[ic];
    } else {
        int idx = (bx - 1024) * 256 + tid;
        const float* p = cw + (size_t)idx * 9;
        float s = 0.f;
        #pragma unroll
        for (int k = 0; k < 9; k++) { float v = p[k]; s += v * v; }
        g_wsum[idx] = s;
    }
}

// ---------------------------------------------------------------------------
// K2: fused prep (A style-scaled fp16 transpose vectorized; B reorder; dcoef)
// ---------------------------------------------------------------------------
__global__ void k_prep(const float* __restrict__ x, const float* __restrict__ cw) {
    __shared__ float s[4680];
    int bx = blockIdx.x, tid = threadIdx.x;
    if (bx < 2048) {
        int b  = bx >> 7;
        int m0 = (bx & 15) * 64;
        int k0 = ((bx >> 4) & 7) * 64;
        #pragma unroll
        for (int it = 0; it < 4; it++) {
            int l = tid + it * 256;
            int ii = l >> 4, jj4 = (l & 15) * 4;
            const float4 xv = *(const float4*)&x[(((size_t)b * IC + k0 + ii) << 10) + m0 + jj4];
            float st = g_styles[b * IC + k0 + ii];
            s[(jj4 + 0) * 65 + ii] = xv.x * st;
            s[(jj4 + 1) * 65 + ii] = xv.y * st;
            s[(jj4 + 2) * 65 + ii] = xv.z * st;
            s[(jj4 + 3) * 65 + ii] = xv.w * st;
        }
        __syncthreads();
        #pragma unroll
        for (int it = 0; it < 8; it++) {
            int l = tid + it * 256;
            int mm = l >> 5, kk = (l & 31) * 2;
            __half2 hv = __floats2half2_rn(s[mm * 65 + kk], s[mm * 65 + kk + 1]);
            *(__half2*)&g_A[(((size_t)b * MM + m0 + mm) << 9) + k0 + kk] = hv;
        }
    } else if (bx < 2560) {
        int oc = bx - 2048;
        for (int l = tid; l < 4608; l += 256) s[l] = cw[(size_t)oc * 4608 + l];
        __syncthreads();
        for (int l = tid; l < 4608; l += 256) {
            int t = l / 512, k = l & 511;
            size_t idx = (((size_t)oc * 9 + t) << 9) + k;
            g_B[idx] = __float2half_rn(s[k * 9 + t]);
        }
    } else {
        int warp = tid >> 5, lane = tid & 31;
        int pair = (bx - 2560) * 8 + warp;
        int b = pair >> 9, oc = pair & 511;
        float part = 0.f;
        #pragma unroll 4
        for (int ic = lane; ic < IC; ic += 32) {
            float st = g_styles[b * IC + ic];
            part += st * st * g_wsum[oc * IC + ic];
        }
        #pragma unroll
        for (int o = 16; o; o >>= 1) part += __shfl_xor_sync(0xffffffffu, part, o);
        if (lane == 0) g_dcoef[pair] = rsqrtf(part + 1e-8f);
    }
}

// ---------------------------------------------------------------------------
// K3: mma.sync fp16 GEMM (R13/R16 configuration — best measured; unchanged).
// ---------------------------------------------------------------------------
__device__ __forceinline__ void load_chunk_g(uint32_t sb, int m0, int n0,
                                             int c, int st, int tid) {
    size_t kc0 = (size_t)c * TKC;
    #pragma unroll
    for (int i = 0; i < 8; i++) {
        int l = tid + i * 512;
        int r = l >> 4, ch = l & 15;
        const __half* gp = g_A + (((size_t)(m0 + r)) << 9) + kc0 + ch * 8;
        cp16(sb + SA(st) + r * 256u + ((ch ^ (r & 7)) * 16u), gp);
    }
    #pragma unroll
    for (int i = 0; i < 4; i++) {
        int l = tid + i * 512;
        int r = l >> 4, ch = l & 15;
        const __half* gp = g_B + (((size_t)(n0 + r)) << 9) + kc0 + ch * 8;
        cp16(sb + SBB(st) + r * 256u + ((ch ^ (r & 7)) * 16u), gp);
    }
    asm volatile("cp.async.commit_group;" ::: "memory");
}

__global__ void __launch_bounds__(512, 1) k_gemm() {
    extern __shared__ char smem[];
    uint32_t sb = smem_u32(smem);
    int tid = threadIdx.x, wid = tid >> 5, lane = tid & 31;
    int n0 = blockIdx.x * TN;
    int m0 = blockIdx.y * TM;

    int wm0 = (wid >> 2) * 64;
    int wn0 = (wid & 3) * 32;

    int mat = lane >> 3, rr = lane & 7;
    int lr  = (mat & 1) * 8 + rr;
    int chi = mat >> 1;

    uint32_t arow = (uint32_t)(wm0 + lr);
    uint32_t brow = (uint32_t)(wn0 + lr);
    uint32_t aswz = arow & 7;
    uint32_t bswz = brow & 7;

    float acc[4][4][4];
    #pragma unroll
    for (int i = 0; i < 4; i++)
        #pragma unroll
        for (int j = 0; j < 4; j++)
            #pragma unroll
            for (int q = 0; q < 4; q++) acc[i][j][q] = 0.f;

    load_chunk_g(sb, m0, n0, 0, 0, tid);

    #pragma unroll 1
    for (int c = 0; c < NKC; c++) {
        int st = c & 1;
        asm volatile("cp.async.wait_group 0;" ::: "memory");
        __syncthreads();
        if (c + 1 < NKC) load_chunk_g(sb, m0, n0, c + 1, st ^ 1, tid);

        #pragma unroll
        for (int s = 0; s < 8; s++) {
            uint32_t kchunk = (uint32_t)(2 * s + chi);
            uint32_t acol = ((kchunk ^ aswz) * 16u);
            uint32_t bcol = ((kchunk ^ bswz) * 16u);

            uint32_t bf[2][4];
            #pragma unroll
            for (int nj2 = 0; nj2 < 2; nj2++)
                ldsm4(bf[nj2], sb + SBB(st) + (brow + nj2 * 16u) * 256u + bcol);

            uint32_t af[4][4];
            #pragma unroll
            for (int mi = 0; mi < 4; mi++)
                ldsm4(af[mi], sb + SA(st) + (arow + mi * 16u) * 256u + acol);

            #pragma unroll
            for (int mi = 0; mi < 4; mi++)
                #pragma unroll
                for (int nj = 0; nj < 4; nj++)
                    mma_fp16(acc[mi][nj], af[mi],
                             bf[nj >> 1][nj & 1], bf[nj >> 1][(nj & 1) + 2]);
        }
    }

    __syncthreads();
    __half* cs = (__half*)smem;
    int g  = lane >> 2;
    int cq = (lane & 3) * 2;
    #pragma unroll
    for (int mi = 0; mi < 4; mi++) {
        #pragma unroll
        for (int nj = 0; nj < 4; nj++) {
            int nl = wn0 + nj * 8 + cq;
            int ml = wm0 + mi * 16 + g;
            cs[nl * EPI_ST + ml]           = __float2half_rn(acc[mi][nj][0]);
            cs[(nl + 1) * EPI_ST + ml]     = __float2half_rn(acc[mi][nj][1]);
            cs[nl * EPI_ST + ml + 8]       = __float2half_rn(acc[mi][nj][2]);
            cs[(nl + 1) * EPI_ST + ml + 8] = __float2half_rn(acc[mi][nj][3]);
        }
    }
    __syncthreads();

    int b    = m0 >> 10;
    int mloc = m0 & 1023;
    __half* gout = g_ct + ((size_t)b * NN + n0) * MM + mloc;
    #pragma unroll
    for (int i = 0; i < 8; i++) {
        int l = tid + i * 512;
        int row = l >> 5, c16 = l & 31;
        uint4 v = *(const uint4*)&cs[row * EPI_ST + c16 * 8];
        *(uint4*)(gout + (size_t)row * MM + c16 * 8) = v;
    }
}

// ---------------------------------------------------------------------------
// K4: separable fused FIR v2 — pass 2 with u-pair row sharing.
// For pair (ue even, uo=ue+1), s=ue/2, rows Rm=s-1, R0=s, R1=s+1:
//   res_e = g1·H0[R0]+g3·H0[R1] + g0·H1[Rm]+g2·H1[R0] + g1·H2[Rm]+g3·H2[R0]
//   res_o = g0·H0[R0]+g2·H0[R1] + g1·H1[R0]+g3·H1[R1] + g0·H2[Rm]+g2·H2[R0]
// 7 row-loads per pair (was 12). Thread = (pair 0..15) x (vg 0..15, v-width 4).
// Pass 1 unchanged (validated).
// ---------------------------------------------------------------------------
#define HROWS 18
#define HST   68
__global__ void __launch_bounds__(256, 5) k_fir(const float* __restrict__ f,
                                                const float* __restrict__ noise,
                                                const float* __restrict__ bias,
                                                float* __restrict__ out) {
    __shared__ __align__(16) float H[3 * HROWS * HST];

    int z  = blockIdx.x;
    int b  = z >> 10;
    int oc = (z >> 1) & 511;
    int uh = z & 1;
    int u0 = uh << 5;
    int hb = uh ? 15 : -1;
    int tid = threadIdx.x;

    float f00 = f[0];
    float rs  = rsqrtf(f00);
    float gv0 = 2.f * f[0] * rs;
    float gv1 = 2.f * f[1] * rs;
    float gv2 = 2.f * f[2] * rs;
    float gv3 = 2.f * f[3] * rs;

    // ---- pass 1: horizontal FIR + j-sum, fused with g_ct load (unchanged) ----
    if (tid < 216) {
        int i   = tid / 72;
        int rem = tid - i * 72;
        int r = rem >> 2, s4 = rem & 3;
        int h = hb + r;

        float Hv[16];
        #pragma unroll
        for (int k = 0; k < 16; k++) Hv[k] = 0.f;

        if (h >= 0 && h < 32) {
            const __half* cb = g_ct + ((size_t)b * NN + (size_t)oc * 9) * MM;
            #pragma unroll
            for (int j = 0; j < 3; j++) {
                const uint2* src = (const uint2*)(cb + (size_t)(i * 3 + j) * MM + h * 32);
                float c[16];
                #pragma unroll
                for (int q = 0; q < 4; q++) {
                    int wb = 8 * s4 - 4 + 4 * q;
                    if (wb >= 0 && wb < 32) {
                        uint2 v = src[wb >> 2];
                        float2 x0 = __half22float2(*(const __half2*)&v.x);
                        float2 x1 = __half22float2(*(const __half2*)&v.y);
                        c[4*q]   = x0.x; c[4*q+1] = x0.y;
                        c[4*q+2] = x1.x; c[4*q+3] = x1.y;
                    } else {
                        c[4*q] = c[4*q+1] = c[4*q+2] = c[4*q+3] = 0.f;
                    }
                }
                #pragma unroll
                for (int k = 0; k < 16; k++) {
                    const int e0 = (j + k + 1) & 1;
                    const int lw = (k - 1 - j + e0) / 2 + 4;
                    float ge0 = e0 ? gv1 : gv0;
                    float ge2 = e0 ? gv3 : gv2;
                    Hv[k] += ge0 * c[lw] + ge2 * c[lw + 1];
                }
            }
        }
        float4* dst = (float4*)&H[(i * HROWS + r) * HST + 16 * s4];
        dst[0] = make_float4(Hv[0],  Hv[1],  Hv[2],  Hv[3]);
        dst[1] = make_float4(Hv[4],  Hv[5],  Hv[6],  Hv[7]);
        dst[2] = make_float4(Hv[8],  Hv[9],  Hv[10], Hv[11]);
        dst[3] = make_float4(Hv[12], Hv[13], Hv[14], Hv[15]);
    }
    __syncthreads();

    // ---- pass 2: vertical FIR, u-paired ----
    float dco = g_dcoef[b * OC + oc];
    int vg = tid & 15;            // v = 4*vg
    int pr = tid >> 4;            // 0..15
    int ue = u0 + 2 * pr;
    int s  = ue >> 1;
    int Rm = (s - 1 - hb) * HST + 4 * vg;
    int R0 = (s     - hb) * HST + 4 * vg;
    int R1 = (s + 1 - hb) * HST + 4 * vg;

    float4 h0a = *(const float4*)&H[0 * HROWS * HST + R0];
    float4 h0b = *(const float4*)&H[0 * HROWS * HST + R1];
    float4 h1m = *(const float4*)&H[1 * HROWS * HST + Rm];
    float4 h1a = *(const float4*)&H[1 * HROWS * HST + R0];
    float4 h1b = *(const float4*)&H[1 * HROWS * HST + R1];
    float4 h2m = *(const float4*)&H[2 * HROWS * HST + Rm];
    float4 h2a = *(const float4*)&H[2 * HROWS * HST + R0];

    float4 re, ro;
    re.x = gv1 * h0a.x + gv3 * h0b.x;
    re.y = gv1 * h0a.y + gv3 * h0b.y;
    re.z = gv1 * h0a.z + gv3 * h0b.z;
    re.w = gv1 * h0a.w + gv3 * h0b.w;
    ro.x = gv0 * h0a.x + gv2 * h0b.x;
    ro.y = gv0 * h0a.y + gv2 * h0b.y;
    ro.z = gv0 * h0a.z + gv2 * h0b.z;
    ro.w = gv0 * h0a.w + gv2 * h0b.w;

    re.x += gv0 * h1m.x + gv2 * h1a.x;
    re.y += gv0 * h1m.y + gv2 * h1a.y;
    re.z += gv0 * h1m.z + gv2 * h1a.z;
    re.w += gv0 * h1m.w + gv2 * h1a.w;
    ro.x += gv1 * h1a.x + gv3 * h1b.x;
    ro.y += gv1 * h1a.y + gv3 * h1b.y;
    ro.z += gv1 * h1a.z + gv3 * h1b.z;
    ro.w += gv1 * h1a.w + gv3 * h1b.w;

    re.x += gv1 * h2m.x + gv3 * h2a.x;
    re.y += gv1 * h2m.y + gv3 * h2a.y;
    re.z += gv1 * h2m.z + gv3 * h2a.z;
    re.w += gv1 * h2m.w + gv3 * h2a.w;
    ro.x += gv0 * h2m.x + gv2 * h2a.x;
    ro.y += gv0 * h2m.y + gv2 * h2a.y;
    ro.z += gv0 * h2m.z + gv2 * h2a.z;
    ro.w += gv0 * h2m.w + gv2 * h2a.w;

    float bs = bias[oc];
    const float4 ne = *(const float4*)(noise + ue * RES + 4 * vg);
    const float4 no = *(const float4*)(noise + (ue + 1) * RES + 4 * vg);
    float4 oe, oo;
    {
        float v;
        v = re.x * dco + ne.x + bs; v = (v > 0.f) ? v : 0.2f * v; oe.x = v * 1.4142135623730951f;
        v = re.y * dco + ne.y + bs; v = (v > 0.f) ? v : 0.2f * v; oe.y = v * 1.4142135623730951f;
        v = re.z * dco + ne.z + bs; v = (v > 0.f) ? v : 0.2f * v; oe.z = v * 1.4142135623730951f;
        v = re.w * dco + ne.w + bs; v = (v > 0.f) ? v : 0.2f * v; oe.w = v * 1.4142135623730951f;
        v = ro.x * dco + no.x + bs; v = (v > 0.f) ? v : 0.2f * v; oo.x = v * 1.4142135623730951f;
        v = ro.y * dco + no.y + bs; v = (v > 0.f) ? v : 0.2f * v; oo.y = v * 1.4142135623730951f;
        v = ro.z * dco + no.z + bs; v = (v > 0.f) ? v : 0.2f * v; oo.z = v * 1.4142135623730951f;
        v = ro.w * dco + no.w + bs; v = (v > 0.f) ? v : 0.2f * v; oo.w = v * 1.4142135623730951f;
    }
    float* obase = out + (((size_t)(b * OC + oc) * RES) + ue) * RES + 4 * vg;
    *(float4*)obase          = oe;
    *(float4*)(obase + RES)  = oo;
}

// ---------------------------------------------------------------------------
extern "C" void kernel_launch(void* const* d_in, const int* in_sizes, int n_in,
                              void* d_out, int out_size) {
    const float* x     = (const float*)d_in[0];
    const float* w     = (const float*)d_in[1];
    const float* aw    = (const float*)d_in[2];
    const float* ab    = (const float*)d_in[3];
    const float* cw    = (const float*)d_in[4];
    const float* bias  = (const float*)d_in[5];
    const float* noise = (const float*)d_in[6];
    const float* f     = (const float*)d_in[7];
    float* out = (float*)d_out;

    cudaFuncSetAttribute(k_gemm, cudaFuncAttributeMaxDynamicSharedMemorySize, SM_TOTAL_G);
    cudaFuncSetAttribute(k_fir, cudaFuncAttributePreferredSharedMemoryCarveout, 100);

    k_sw   <<<2048, 256>>>(w, aw, ab, cw);
    k_prep <<<3584, 256>>>(x, cw);
    k_gemm <<<dim3(NN / TN, MF / TM), 512, SM_TOTAL_G>>>();
    k_fir  <<<BATCH * OC * 2, 256>>>(f, noise, bias, out);
}